// round 7
// baseline (speedup 1.0000x reference)
#include <cuda_runtime.h>

#define TILE_B   4
#define THREADS  256
#define NB       8192
#define NIO      64

// Precomputed per-(o,i) coefficient tables, laid out [i][o] for coalesced
// per-o lane reads.  A = {c1', b2', b3', b4}, B = {c5..c8} (gamma/64 folded).
__device__ float4 g_tabA[NIO * NIO];
__device__ float4 g_tabB[NIO * NIO];

__device__ __forceinline__ float ex2f_(float x) {
    float y; asm("ex2.approx.ftz.f32 %0, %1;" : "=f"(y) : "f"(x)); return y;
}
__device__ __forceinline__ float lg2f_(float x) {
    float y; asm("lg2.approx.ftz.f32 %0, %1;" : "=f"(y) : "f"(x)); return y;
}

// ---------------------------------------------------------------------------
// Setup: evaluate the 8 cubic splines at w_norm for every (o,i) pair and fold
// all constant factors so the main loop is pure EX2/LG2 + FFMA.
// breaks/coefs staged through smem (were ~200 scattered LDGs per thread).
// ---------------------------------------------------------------------------
__global__ void setup_kernel(const float* __restrict__ raw_gamma,
                             const float* __restrict__ w,
                             const float* __restrict__ breaks,
                             const float* __restrict__ coefs,
                             const float* __restrict__ mu_p,
                             const float* __restrict__ sig_p)
{
    __shared__ float sbr[8 * 20];
    __shared__ float scf[8 * 19 * 4];

    int t = threadIdx.x;
    if (t < 160) sbr[t] = breaks[t];
    for (int k = t; k < 8 * 19 * 4; k += blockDim.x) scf[k] = coefs[k];
    __syncthreads();

    int tid = blockIdx.x * blockDim.x + t;
    if (tid >= NIO * NIO) return;
    int o = tid >> 6;
    int i = tid & 63;

    float mu  = *mu_p;
    float sig = *sig_p;
    float wv  = w[tid];                       // w[o][i]
    float wc  = fminf(fmaxf(wv, -5.5f), 37.9f);
    float wn  = (wc - mu) / sig;

    float b[8];
#pragma unroll
    for (int s = 0; s < 8; s++) {
        const float* br = sbr + s * 20;
        float blo = br[0];
        float bhi = br[19] - 1e-6f;
        float wl  = fminf(fmaxf(wn, blo), bhi);
        int cnt = 0;
#pragma unroll
        for (int k = 0; k < 20; k++) cnt += (br[k] < wl) ? 1 : 0;
        int idx = cnt - 1;
        idx = max(idx, 0);
        idx = min(idx, 18);
        const float* a = scf + (s * 19 + idx) * 4;
        float tt = wl - br[idx];
        b[s] = ((a[0] * tt + a[1]) * tt + a[2]) * tt + a[3];
    }

    float rg = raw_gamma[tid];
    float g  = (rg > 20.f) ? rg : log1pf(expf(rg));   // softplus
    float scale = g * (1.0f / 64.0f);

    const float LN2   = 0.6931471805599453f;
    const float LOG2E = 1.4426950408889634f;

    float4 A, Bq;
    A.x = b[0] * scale * LN2;   // c1'
    A.y = b[1] * LN2;           // b2'
    A.z = b[2] * LOG2E;         // b3'
    A.w = b[3];                 // b4
    Bq.x = b[4] * scale;
    Bq.y = b[5] * scale;
    Bq.z = b[6] * scale;
    Bq.w = b[7] * scale;

    int p = i * NIO + o;        // [i][o] layout
    g_tabA[p] = A;
    g_tabB[p] = Bq;
}

// ---------------------------------------------------------------------------
// Main kernel.  Block = 256 threads = 8 warps, TILE_B=4 rows, grid=2048.
// Warp wp -> row (wp>>1), o-half (wp&1).  Single 64-bit activity mask,
// drained from BOTH ends (chain0 = LSB side, chain1 = MSB side) so the two
// independent MUFU chains stay balanced to within 1 step.  Software
// pipelined: xv + A for step k+1 are fetched before computing step k; B is
// loaded at compute time (its poly consumers sit ~80 cycles into the chain).
// ---------------------------------------------------------------------------
__global__ __launch_bounds__(THREADS, 5)
void main_kernel(const float* __restrict__ x, float* __restrict__ out)
{
    __shared__ float xs[TILE_B * 64];

    const int tid   = threadIdx.x;
    const long base = (long)blockIdx.x * (TILE_B * 64);

    // Phase 1: load x tile + relu (one element per thread, coalesced)
    xs[tid] = fmaxf(x[base + tid], 0.f);
    __syncthreads();

    const int lane = tid & 31;
    const int wp   = tid >> 5;
    const int r    = wp >> 1;
    const int o    = lane + (wp & 1) * 32;

    const float* xrow = xs + r * 64;
    float v0 = xrow[lane];
    float v1 = xrow[lane + 32];
    unsigned lo = __ballot_sync(0xffffffffu, v0 > 0.f);
    unsigned hi = __ballot_sync(0xffffffffu, v1 > 0.f);
    unsigned long long m = (unsigned long long)lo |
                           ((unsigned long long)hi << 32);

    const float4* tA = g_tabA + o;
    const float4* tB = g_tabB + o;

    float acc0 = 0.f, acc1 = 0.f;

    // COMPUTE on prefetched xv/A; B loaded here (hidden under the MUFU chain)
#define CHAIN(ACC, XV, A, II)                                             \
    {                                                                     \
        float4 Bq = __ldg(tB + (II) * NIO);                               \
        float e  = ex2f_((A).z * (XV)) - 1.f;                             \
        float p  = ex2f_((A).w * lg2f_(e));                               \
        float l1 = lg2f_(1.f + p);                                        \
        float l2 = lg2f_(fmaf((A).y, l1, 1.f));                           \
        ACC = fmaf((A).x, l2, ACC);                                       \
        float x2 = (XV) * (XV);                                           \
        float pA = fmaf(Bq.z, x2, Bq.x);                                  \
        float pB = fmaf(Bq.w, x2, Bq.y);                                  \
        ACC = fmaf(fmaf(pB, (XV), pA), (XV), ACC);                        \
    }

    int cnt = __popcll(m);
    int nb  = cnt >> 1;          // balanced two-sided steps

    if (nb > 0) {
        // Prologue: fetch step 0 for both chains (low end / high end)
        int i0 = __ffsll(m) - 1;         m &= m - 1;
        int i1 = 63 - __clzll(m);        m ^= (1ull << i1);
        float  xv0 = xrow[i0];
        float  xv1 = xrow[i1];
        float4 A0  = __ldg(tA + i0 * NIO);
        float4 A1  = __ldg(tA + i1 * NIO);
        int ci0 = i0, ci1 = i1;

        for (int k = 1; k < nb; k++) {
            // FETCH next step
            int j0 = __ffsll(m) - 1;     m &= m - 1;
            int j1 = 63 - __clzll(m);    m ^= (1ull << j1);
            float  nxv0 = xrow[j0];
            float  nxv1 = xrow[j1];
            float4 nA0  = __ldg(tA + j0 * NIO);
            float4 nA1  = __ldg(tA + j1 * NIO);

            // COMPUTE current step (2 independent MUFU chains)
            CHAIN(acc0, xv0, A0, ci0);
            CHAIN(acc1, xv1, A1, ci1);

            // rotate
            xv0 = nxv0; A0 = nA0; ci0 = j0;
            xv1 = nxv1; A1 = nA1; ci1 = j1;
        }
        // Epilogue
        CHAIN(acc0, xv0, A0, ci0);
        CHAIN(acc1, xv1, A1, ci1);
    }

    // Leftover (cnt odd): at most one step
    if (cnt & 1) {
        int i0 = __ffsll(m) - 1;
        float  xv = xrow[i0];
        float4 A  = __ldg(tA + i0 * NIO);
        CHAIN(acc0, xv, A, i0);
    }
#undef CHAIN

    out[base + r * 64 + o] = acc0 + acc1;
}

// ---------------------------------------------------------------------------
extern "C" void kernel_launch(void* const* d_in, const int* in_sizes, int n_in,
                              void* d_out, int out_size)
{
    const float* x   = (const float*)d_in[0];
    const float* rg  = (const float*)d_in[1];
    const float* w   = (const float*)d_in[2];
    const float* br  = (const float*)d_in[3];
    const float* cf  = (const float*)d_in[4];
    const float* mu  = (const float*)d_in[5];
    const float* sg  = (const float*)d_in[6];
    float* out = (float*)d_out;

    setup_kernel<<<(NIO * NIO + 255) / 256, 256>>>(rg, w, br, cf, mu, sg);
    main_kernel<<<NB / TILE_B, THREADS>>>(x, out);
}